// round 7
// baseline (speedup 1.0000x reference)
#include <cuda_runtime.h>
#include <math.h>

#define NN 80
#define PAIRS (NN * NN)          // 6400
#define MAX_ITERS 60
#define TOL 1e-3f
#define TPB 256

__global__ void zero_out(float* __restrict__ out) {
    out[threadIdx.x] = 0.0f;     // d_out is poisoned; we accumulate atomically
}

__global__ __launch_bounds__(TPB, 5)
void power_iter_kernel(const float* __restrict__ r_zeros,
                       const float* __restrict__ r_const,
                       const float* __restrict__ t_paths,
                       const float* __restrict__ weights_t,
                       const float* __restrict__ weights_r,
                       float* __restrict__ out) {
    __shared__ float As2[NN * 16]; // A cols 64..79 (5 KB) — evicted from regs
    __shared__ float v[NN];        // current eigenvector estimate
    __shared__ float wv[NN];       // w = A v
    __shared__ float red_ww[8];    // per-warp partials of w.w
    __shared__ float red_vw[8];    // per-warp partials of v.w
    __shared__ float s_n2;         // broadcast: ||w||^2
    __shared__ float s_ev;         // broadcast: v . (A v)

    const int p    = blockIdx.x;
    const int tid  = threadIdx.x;
    const int warp = tid >> 5;
    const int lane = tid & 31;

    // ---- Build A = weights_r * r_zeros + r_const.
    // Warp w owns rows {w, w+8, ..., w+72}. Cols 0..63 -> registers
    // (lane, lane+32); cols 64..79 -> shared As2 (lanes 0..15).
    const size_t base = (size_t)p * (NN * NN);
    const float* __restrict__ rz = r_zeros   + base;
    const float* __restrict__ rc = r_const   + base;
    const float* __restrict__ wr = weights_r + base;

    float a0[10], a1[10];
    #pragma unroll
    for (int r = 0; r < 10; ++r) {
        const int row = warp + (r << 3);
        const int o0  = row * NN + lane;
        const int o1  = o0 + 32;
        a0[r] = fmaf(__ldcs(wr + o0), __ldcs(rz + o0), __ldcs(rc + o0));
        a1[r] = fmaf(__ldcs(wr + o1), __ldcs(rz + o1), __ldcs(rc + o1));
        if (lane < 16) {
            const int o2 = o0 + 64;
            As2[row * 16 + lane] =
                fmaf(__ldcs(wr + o2), __ldcs(rz + o2), __ldcs(rc + o2));
        }
    }

    if (tid < NN) v[tid] = 0.11180339887498949f;  // 1/sqrt(80)
    __syncthreads();   // As2 + v visible

    // Fused matvec + dots: wv = A v ; s_n2 = wv.wv ; s_ev = v.wv
    auto mv = [&]() {
        const float vr0 = v[lane];
        const float vr1 = v[lane + 32];
        const float vr2 = (lane < 16) ? v[lane + 64] : 0.0f;
        float ww = 0.0f, vwacc = 0.0f;
        #pragma unroll
        for (int r = 0; r < 10; ++r) {
            const int row = warp + (r << 3);
            float s = a0[r] * vr0;
            s = fmaf(a1[r], vr1, s);
            if (lane < 16) s = fmaf(As2[row * 16 + lane], vr2, s);
            #pragma unroll
            for (int off = 16; off; off >>= 1)
                s += __shfl_xor_sync(0xFFFFFFFFu, s, off);
            if (lane == 0) {
                wv[row] = s;
                ww    = fmaf(s, s, ww);
                vwacc = fmaf(v[row], s, vwacc);
            }
        }
        if (lane == 0) { red_ww[warp] = ww; red_vw[warp] = vwacc; }
        __syncthreads();
        if (tid == 0) {
            float A = 0.0f, B = 0.0f;
            #pragma unroll
            for (int k = 0; k < 8; ++k) { A += red_ww[k]; B += red_vw[k]; }
            s_n2 = A; s_ev = B;
        }
        __syncthreads();
    };

    // ---- ev0 = v0 . (A v0)
    mv();
    float ev = s_ev;

    // ---- scan body x60 with convergence break (v updated on converging step)
    for (int it = 0; it < MAX_ITERS; ++it) {
        const float inv = 1.0f / sqrtf(s_n2);
        if (tid < NN) v[tid] = wv[tid] * inv;    // v_new = Av / ||Av||
        __syncthreads();
        mv();                                     // wv = A v_new ; s_ev = v_new.wv
        const float ev_new = s_ev;
        if (fabsf(ev - ev_new) < TOL) break;      // uniform (shared broadcast)
        ev = ev_new;
    }

    // ---- out[i] += v[i] * (T[p] / v[src]),  src = p / n  (atomic accumulate)
    if (tid < NN) {
        const float tval = weights_t[p] * t_paths[p];
        const float coef = tval / v[p / NN];
        atomicAdd(&out[tid], v[tid] * coef);
    }
}

extern "C" void kernel_launch(void* const* d_in, const int* in_sizes, int n_in,
                              void* d_out, int out_size) {
    // metadata order: 0:x (unused), 1:r_zeros, 2:r_const, 3:t_paths,
    //                 4:weights_t, 5:weights_r
    const float* r_zeros   = (const float*)d_in[1];
    const float* r_const   = (const float*)d_in[2];
    const float* t_paths   = (const float*)d_in[3];
    const float* weights_t = (const float*)d_in[4];
    const float* weights_r = (const float*)d_in[5];
    float* out = (float*)d_out;

    zero_out<<<1, NN>>>(out);
    power_iter_kernel<<<PAIRS, TPB>>>(r_zeros, r_const, t_paths, weights_t,
                                      weights_r, out);
}